// round 2
// baseline (speedup 1.0000x reference)
#include <cuda_runtime.h>
#include <math.h>

#define Bq 64
#define Tq 512
#define Iq 1024
#define Hq 1024
#define G4 4096          // 4*H
#define NBLK 128         // persistent blocks (<=148 SMs, all resident)
#define KC 64            // k-chunk for h tiles

// ---- scratch (static __device__; no allocations allowed) ----
__device__ float g_xproj[(size_t)Tq * Bq * G4];   // [t][b][4H]  512 MB
__device__ float g_hT[2][Hq * Bq];                // transposed h: [j][b], ping-pong

// ---- software grid barrier state ----
__device__ unsigned g_bar_count = 0;
__device__ volatile unsigned g_bar_phase = 0;

// ---------------------------------------------------------------
// Phase 1: x_proj[t][b][n] = sum_k x[b,t,k] * Wx[k,n] + bias[n]
// M = B*T = 32768 (row m = b*T + t), K = 1024, N = 4096
// 64x64 tile, BK=16, 256 threads, 4x4 micro-tile
// ---------------------------------------------------------------
__global__ void gemm_xproj_kernel(const float* __restrict__ A,
                                  const float* __restrict__ Bw,
                                  const float* __restrict__ bias) {
    const int K = Iq, N = G4;
    __shared__ float As[16][68];
    __shared__ float Bs[16][64];

    const int tx = threadIdx.x;    // 0..15 -> n micro
    const int ty = threadIdx.y;    // 0..15 -> m micro
    const int tid = ty * 16 + tx;
    const int row0 = blockIdx.y * 64;
    const int col0 = blockIdx.x * 64;

    float acc[4][4];
#pragma unroll
    for (int i = 0; i < 4; i++)
#pragma unroll
        for (int j = 0; j < 4; j++) acc[i][j] = 0.f;

    for (int k0 = 0; k0 < K; k0 += 16) {
#pragma unroll
        for (int i = tid; i < 64 * 16; i += 256) {
            int m = i >> 4, k = i & 15;
            As[k][m] = A[(size_t)(row0 + m) * K + k0 + k];
        }
#pragma unroll
        for (int i = tid; i < 16 * 64; i += 256) {
            int k = i >> 6, n = i & 63;
            Bs[k][n] = Bw[(size_t)(k0 + k) * N + col0 + n];
        }
        __syncthreads();

#pragma unroll
        for (int k = 0; k < 16; k++) {
            float4 a4 = *reinterpret_cast<const float4*>(&As[k][ty * 4]);
            float4 b4 = *reinterpret_cast<const float4*>(&Bs[k][tx * 4]);
            float av[4] = {a4.x, a4.y, a4.z, a4.w};
            float bv[4] = {b4.x, b4.y, b4.z, b4.w};
#pragma unroll
            for (int i = 0; i < 4; i++)
#pragma unroll
                for (int j = 0; j < 4; j++)
                    acc[i][j] = fmaf(av[i], bv[j], acc[i][j]);
        }
        __syncthreads();
    }

#pragma unroll
    for (int i = 0; i < 4; i++) {
        int m = row0 + ty * 4 + i;
        int b = m >> 9;           // m / T
        int t = m & 511;          // m % T
        size_t base = ((size_t)t * Bq + b) * G4;
#pragma unroll
        for (int j = 0; j < 4; j++) {
            int n = col0 + tx * 4 + j;
            g_xproj[base + n] = acc[i][j] + bias[n];
        }
    }
}

// ---------------------------------------------------------------
// Grid barrier (all NBLK blocks resident -> safe)
// ---------------------------------------------------------------
__device__ __forceinline__ void grid_sync(unsigned expected) {
    __syncthreads();
    if (threadIdx.x == 0) {
        __threadfence();
        unsigned a = atomicAdd(&g_bar_count, 1u);
        if (a == (unsigned)(gridDim.x - 1)) {
            g_bar_count = 0;
            __threadfence();
            g_bar_phase = expected;
        } else {
            while (g_bar_phase != expected) __nanosleep(64);
        }
        __threadfence();
    }
    __syncthreads();
}

// ---------------------------------------------------------------
// Persistent recurrent kernel.
// Block bx owns h-columns j0..j0+7, gate columns {g*1024 + j0 + 0..7}, g=0..3
// SMEM: Ws[1024][32] (128KB, loaded once) + Hs double buffer (2*16KB) + Gs (8KB)
// ---------------------------------------------------------------
__global__ void __launch_bounds__(256, 1)
lstm_persistent_kernel(const float* __restrict__ Wh, float* __restrict__ out) {
    extern __shared__ float smem[];
    float* Ws  = smem;                // 1024*32
    float* Hs0 = Ws + 1024 * 32;      // 64*64
    float* Hs1 = Hs0 + KC * 64;       // 64*64
    float* Gs  = Hs1 + KC * 64;       // 64*32

    const int tid = threadIdx.x;
    const int tx  = tid & 7;          // col quad (4 cols)
    const int ty  = tid >> 3;         // 0..31, batch pair
    const int j0  = blockIdx.x * 8;

    // ---- load Wh slice into SMEM (once) ----
    for (int idx = tid; idx < 1024 * 32; idx += 256) {
        int k = idx >> 5, c = idx & 31;
        int col = (c >> 3) * 1024 + j0 + (c & 7);
        Ws[idx] = Wh[(size_t)k * G4 + col];
    }
    // ---- zero my rows of hT[0] ----
    for (int idx = tid; idx < 8 * 64; idx += 256)
        g_hT[0][j0 * 64 + idx] = 0.f;

    // c state in registers: thread handles (b = t/8, j = t%8) for p = tid, tid+256
    float creg0 = 0.f, creg1 = 0.f;

    // barrier bookkeeping
    unsigned phase0 = 0;
    if (tid == 0) phase0 = g_bar_phase;   // read before any arrival: safe
    unsigned nbar = 0;

    nbar++; grid_sync(phase0 + nbar);     // hT[0] zeros visible everywhere

    // epilogue column mapping for this thread
    const int gc0 = (tx >> 1) * 1024 + j0 + (tx & 1) * 4;  // global gate col of quad start

    for (int t = 0; t < Tq; t++) {
        const float* hT = g_hT[t & 1];
        const float4* hT4 = reinterpret_cast<const float4*>(hT);

        float acc[2][4];
#pragma unroll
        for (int i = 0; i < 2; i++)
#pragma unroll
            for (int q = 0; q < 4; q++) acc[i][q] = 0.f;

        // preload chunk 0 into Hs0
        {
            float4* dst = reinterpret_cast<float4*>(Hs0);
#pragma unroll
            for (int i = 0; i < 4; i++) {
                int u = tid + i * 256;            // float4 index within chunk (k*16+q)
                dst[u] = hT4[u];                  // chunk 0: k0 = 0
            }
        }
        float* cur = Hs0;
        float* nxt = Hs1;

        for (int ch = 0; ch < Hq / KC; ch++) {
            __syncthreads();                      // cur tile visible
            float4 pre[4];
            if (ch < Hq / KC - 1) {
                size_t base4 = (size_t)(ch + 1) * KC * 16;   // float4 units
#pragma unroll
                for (int i = 0; i < 4; i++)
                    pre[i] = hT4[base4 + tid + i * 256];
            }
            const int kbase = ch * KC;
#pragma unroll 16
            for (int kk = 0; kk < KC; kk++) {
                float4 w4 = *reinterpret_cast<const float4*>(&Ws[(kbase + kk) * 32 + tx * 4]);
                float2 h2 = *reinterpret_cast<const float2*>(&cur[kk * 64 + ty * 2]);
                float hv[2] = {h2.x, h2.y};
                float wv[4] = {w4.x, w4.y, w4.z, w4.w};
#pragma unroll
                for (int i = 0; i < 2; i++)
#pragma unroll
                    for (int q = 0; q < 4; q++)
                        acc[i][q] = fmaf(hv[i], wv[q], acc[i][q]);
            }
            if (ch < Hq / KC - 1) {
                float4* dst = reinterpret_cast<float4*>(nxt);
#pragma unroll
                for (int i = 0; i < 4; i++)
                    dst[tid + i * 256] = pre[i];
                float* tmp = cur; cur = nxt; nxt = tmp;
            }
        }

        // epilogue: add xproj, store to Gs
#pragma unroll
        for (int i = 0; i < 2; i++) {
            int b = ty * 2 + i;
            float4 xp = *reinterpret_cast<const float4*>(
                &g_xproj[((size_t)t * Bq + b) * G4 + gc0]);
            float4 v = make_float4(acc[i][0] + xp.x, acc[i][1] + xp.y,
                                   acc[i][2] + xp.z, acc[i][3] + xp.w);
            *reinterpret_cast<float4*>(&Gs[b * 32 + tx * 4]) = v;
        }
        __syncthreads();

        // pointwise: thread handles p = tid (b=tid/8, j=tid%8) and p+256 (b+32, j)
        float* hTn = g_hT[(t + 1) & 1];
        {
            int j = tid & 7;
            int b = tid >> 3;                 // 0..31
#pragma unroll
            for (int half = 0; half < 2; half++) {
                int bb = b + half * 32;
                float ig = Gs[bb * 32 + 0 * 8 + j];
                float fg = Gs[bb * 32 + 1 * 8 + j];
                float gg = Gs[bb * 32 + 2 * 8 + j];
                float og = Gs[bb * 32 + 3 * 8 + j];
                float iv = 1.f / (1.f + __expf(-ig));
                float fv = 1.f / (1.f + __expf(-fg));
                float gv = tanhf(gg);
                float ov = 1.f / (1.f + __expf(-og));
                float cprev = half ? creg1 : creg0;
                float c = fv * cprev + iv * gv;
                float h = ov * tanhf(c);
                if (half) creg1 = c; else creg0 = c;
                out[((size_t)bb * Tq + t) * Hq + j0 + j] = h;
                hTn[(j0 + j) * 64 + bb] = h;
            }
        }

        nbar++; grid_sync(phase0 + nbar);
    }
}

// ---------------------------------------------------------------
extern "C" void kernel_launch(void* const* d_in, const int* in_sizes, int n_in,
                              void* d_out, int out_size) {
    const float* x    = (const float*)d_in[0];   // [B, T, I]
    const float* Wx   = (const float*)d_in[1];   // [I, 4H]
    const float* Wh   = (const float*)d_in[2];   // [H, 4H]
    const float* bias = (const float*)d_in[3];   // [4H]
    float* out = (float*)d_out;                  // [B, T, H]

    static int smem_set = 0;
    const int smem_bytes = (1024 * 32 + 2 * KC * 64 + 64 * 32) * sizeof(float);
    if (!smem_set) {
        cudaFuncSetAttribute(lstm_persistent_kernel,
                             cudaFuncAttributeMaxDynamicSharedMemorySize, smem_bytes);
        smem_set = 1;
    }

    dim3 g1(G4 / 64, (Bq * Tq) / 64);
    gemm_xproj_kernel<<<g1, dim3(16, 16)>>>(x, Wx, bias);

    lstm_persistent_kernel<<<NBLK, 256, smem_bytes>>>(Wh, out);
}

// round 3
// speedup vs baseline: 1.0273x; 1.0273x over previous
#include <cuda_runtime.h>
#include <math.h>

#define Bq 64
#define Tq 512
#define Iq 1024
#define Hq 1024
#define G4 4096          // 4*H
#define NBLK 128         // persistent blocks, 1/SM (<=148), all resident

// ---- scratch (static __device__; no allocations allowed) ----
__device__ float g_xproj[(size_t)Tq * Bq * G4];   // [t][b][4H]
__device__ float g_hT[2][Hq * Bq];                // transposed h: [j][b], ping-pong

// ---- software grid barrier state ----
__device__ unsigned g_bar_count = 0;
__device__ volatile unsigned g_bar_phase = 0;

// ---------------------------------------------------------------
// Phase 1: x_proj[t][b][n] = sum_k x[b,t,k] * Wx[k,n] + bias[n]
// M = B*T = 32768 (m = b*T + t), K = 1024, N = 4096
// 128x128 tile, BK=16, 256 threads, 8x8 micro (4+4 split), double-buffered
// ---------------------------------------------------------------
__global__ void __launch_bounds__(256, 2)
gemm_xproj_kernel(const float* __restrict__ A,
                  const float* __restrict__ Bw,
                  const float* __restrict__ bias) {
    const int K = Iq, N = G4;
    __shared__ float As[2][16][132];   // [k][m] transposed, padded
    __shared__ float Bs[2][16][128];   // [k][n]

    const int tid = threadIdx.x;
    const int tx = tid & 15;           // n-group
    const int ty = tid >> 4;           // m-group
    const int row0 = blockIdx.y * 128;
    const int col0 = blockIdx.x * 128;

    // loader mapping
    const int am  = tid >> 1;          // 0..127 (A row within tile)
    const int ak  = (tid & 1) * 8;     // 0 or 8 (k offset)
    const int bk0 = tid >> 5;          // 0..7   (B row within tile; +8 for 2nd)
    const int bn4 = (tid & 31) * 4;    // B col offset (floats)

    const float* Aptr = A + (size_t)(row0 + am) * K + ak;
    const float* Bptr = Bw + (size_t)bk0 * N + col0 + bn4;

    float acc[8][8];
#pragma unroll
    for (int i = 0; i < 8; i++)
#pragma unroll
        for (int j = 0; j < 8; j++) acc[i][j] = 0.f;

    // prologue: load k0 = 0 into buffer 0
    {
        float4 a0 = *(const float4*)(Aptr + 0);
        float4 a1 = *(const float4*)(Aptr + 4);
        float4 b0 = *(const float4*)(Bptr);
        float4 b1 = *(const float4*)(Bptr + (size_t)8 * N);
        As[0][ak + 0][am] = a0.x; As[0][ak + 1][am] = a0.y;
        As[0][ak + 2][am] = a0.z; As[0][ak + 3][am] = a0.w;
        As[0][ak + 4][am] = a1.x; As[0][ak + 5][am] = a1.y;
        As[0][ak + 6][am] = a1.z; As[0][ak + 7][am] = a1.w;
        *(float4*)&Bs[0][bk0][bn4]     = b0;
        *(float4*)&Bs[0][bk0 + 8][bn4] = b1;
    }
    __syncthreads();

    for (int k0 = 0; k0 < K; k0 += 16) {
        const int buf = (k0 >> 4) & 1;
        const bool next = (k0 + 16) < K;
        float4 na0, na1, nb0, nb1;
        if (next) {
            const float* Ap = Aptr + k0 + 16;
            na0 = *(const float4*)Ap;
            na1 = *(const float4*)(Ap + 4);
            const float* Bp = Bptr + (size_t)(k0 + 16) * N;
            nb0 = *(const float4*)Bp;
            nb1 = *(const float4*)(Bp + (size_t)8 * N);
        }
#pragma unroll
        for (int kk = 0; kk < 16; kk++) {
            float a8[8], b8[8];
            *(float4*)&a8[0] = *(const float4*)&As[buf][kk][ty * 4];
            *(float4*)&a8[4] = *(const float4*)&As[buf][kk][64 + ty * 4];
            *(float4*)&b8[0] = *(const float4*)&Bs[buf][kk][tx * 4];
            *(float4*)&b8[4] = *(const float4*)&Bs[buf][kk][64 + tx * 4];
#pragma unroll
            for (int i = 0; i < 8; i++)
#pragma unroll
                for (int j = 0; j < 8; j++)
                    acc[i][j] = fmaf(a8[i], b8[j], acc[i][j]);
        }
        if (next) {
            const int nb = buf ^ 1;
            As[nb][ak + 0][am] = na0.x; As[nb][ak + 1][am] = na0.y;
            As[nb][ak + 2][am] = na0.z; As[nb][ak + 3][am] = na0.w;
            As[nb][ak + 4][am] = na1.x; As[nb][ak + 5][am] = na1.y;
            As[nb][ak + 6][am] = na1.z; As[nb][ak + 7][am] = na1.w;
            *(float4*)&Bs[nb][bk0][bn4]     = nb0;
            *(float4*)&Bs[nb][bk0 + 8][bn4] = nb1;
            __syncthreads();
        }
    }

    // epilogue: bias add + write to [t][b][n] layout
    float4 bias_lo = *(const float4*)&bias[col0 + tx * 4];
    float4 bias_hi = *(const float4*)&bias[col0 + 64 + tx * 4];
#pragma unroll
    for (int i = 0; i < 8; i++) {
        int m = row0 + ((i < 4) ? (ty * 4 + i) : (64 + ty * 4 + i - 4));
        int b = m >> 9;             // m / T
        int t = m & 511;            // m % T
        size_t base = ((size_t)t * Bq + b) * G4 + col0;
        float4 lo = make_float4(acc[i][0] + bias_lo.x, acc[i][1] + bias_lo.y,
                                acc[i][2] + bias_lo.z, acc[i][3] + bias_lo.w);
        float4 hi = make_float4(acc[i][4] + bias_hi.x, acc[i][5] + bias_hi.y,
                                acc[i][6] + bias_hi.z, acc[i][7] + bias_hi.w);
        *(float4*)&g_xproj[base + tx * 4]      = lo;
        *(float4*)&g_xproj[base + 64 + tx * 4] = hi;
    }
}

// ---------------------------------------------------------------
// Grid barrier (all NBLK blocks resident -> safe)
// __threadfence() emits gpu-scope fence -> CCTL.IVALL (L1D invalidate),
// which is what makes cross-SM hT reads coherent.
// ---------------------------------------------------------------
__device__ __forceinline__ void grid_sync(unsigned expected) {
    __syncthreads();
    if (threadIdx.x == 0) {
        __threadfence();
        unsigned a = atomicAdd(&g_bar_count, 1u);
        if (a == (unsigned)(gridDim.x - 1)) {
            g_bar_count = 0;
            __threadfence();
            g_bar_phase = expected;
        } else {
            while (g_bar_phase != expected) __nanosleep(64);
        }
        __threadfence();
    }
    __syncthreads();
}

// ---------------------------------------------------------------
// Persistent recurrent kernel.
// Block bx owns h-cols j0..j0+7 -> gate cols {g*1024 + j0 + 0..7}, g=0..3.
// Warp w = k-chunk [w*128, w*128+128); lane = gate-col c (0..31).
// Weights: SMEM, one conflict-free LDS.32 per (k, lane).
// h: broadcast LDG.128 from global hT (L2-resident).
// 64 accumulators/lane (one per batch row). Partials reduced via padded SMEM.
// ---------------------------------------------------------------
__global__ void __launch_bounds__(256, 1)
lstm_persistent_kernel(const float* __restrict__ Wh, float* __restrict__ out) {
    extern __shared__ float smem[];
    float* Ws = smem;                 // [1024][32]   128 KB
    float* Ps = Ws + 1024 * 32;       // [8][64][40]   80 KB (pad 40 -> bank-clean)

    const int tid  = threadIdx.x;
    const int w    = tid >> 5;
    const int lane = tid & 31;
    const int j0   = blockIdx.x * 8;

    // ---- load Wh slice into SMEM (once) ----
    for (int idx = tid; idx < 1024 * 32; idx += 256) {
        int k = idx >> 5, c = idx & 31;
        int col = (c >> 3) * 1024 + j0 + (c & 7);
        Ws[idx] = Wh[(size_t)k * G4 + col];
    }
    // ---- zero my rows of hT[0] ----
    for (int idx = tid; idx < 8 * 64; idx += 256)
        g_hT[0][j0 * 64 + idx] = 0.f;

    float creg[2] = {0.f, 0.f};

    unsigned phase0 = 0;
    if (tid == 0) phase0 = g_bar_phase;
    unsigned nbar = 0;
    nbar++; grid_sync(phase0 + nbar);   // hT[0] zeros + Ws visible

    const int kbase = w * 128;

    for (int t = 0; t < Tq; t++) {
        const float* hT = g_hT[t & 1];

        float acc[64];
#pragma unroll
        for (int i = 0; i < 64; i++) acc[i] = 0.f;

        const float* WsK = Ws + kbase * 32 + lane;
#pragma unroll 2
        for (int kk = 0; kk < 128; kk++) {
            float wv = WsK[kk * 32];                          // LDS.32, conflict-free
            const float4* hp = (const float4*)(hT + (size_t)(kbase + kk) * 64);
#pragma unroll
            for (int bq = 0; bq < 16; bq++) {
                float4 h4 = hp[bq];                           // broadcast LDG.128
                acc[bq * 4 + 0] = fmaf(h4.x, wv, acc[bq * 4 + 0]);
                acc[bq * 4 + 1] = fmaf(h4.y, wv, acc[bq * 4 + 1]);
                acc[bq * 4 + 2] = fmaf(h4.z, wv, acc[bq * 4 + 2]);
                acc[bq * 4 + 3] = fmaf(h4.w, wv, acc[bq * 4 + 3]);
            }
        }

        // ---- store partials: Ps[w][b][lane], row stride 40 ----
        float* Pw = Ps + (size_t)(w * 64) * 40 + lane;
#pragma unroll
        for (int b = 0; b < 64; b++) Pw[b * 40] = acc[b];
        __syncthreads();

        // ---- reduce 8 partials + xproj + pointwise cell ----
        float* hTn = g_hT[(t + 1) & 1];
#pragma unroll
        for (int half = 0; half < 2; half++) {
            int pp = tid + half * 256;      // 0..511
            int b  = pp >> 3;               // 0..63
            int jj = pp & 7;

            float gsum[4] = {0.f, 0.f, 0.f, 0.f};
#pragma unroll
            for (int ww = 0; ww < 8; ww++) {
                const float* Pr = Ps + (size_t)(ww * 64 + b) * 40 + jj;
#pragma unroll
                for (int g = 0; g < 4; g++) gsum[g] += Pr[g * 8];
            }
            size_t xbase = ((size_t)t * Bq + b) * G4 + j0 + jj;
            float ig = gsum[0] + g_xproj[xbase];
            float fg = gsum[1] + g_xproj[xbase + 1024];
            float gg = gsum[2] + g_xproj[xbase + 2048];
            float og = gsum[3] + g_xproj[xbase + 3072];

            float iv = 1.f / (1.f + __expf(-ig));
            float fv = 1.f / (1.f + __expf(-fg));
            float gv = tanhf(gg);
            float ov = 1.f / (1.f + __expf(-og));

            float c = fv * creg[half] + iv * gv;
            float h = ov * tanhf(c);
            creg[half] = c;

            out[((size_t)b * Tq + t) * Hq + j0 + jj] = h;
            hTn[(j0 + jj) * 64 + b] = h;
        }

        nbar++; grid_sync(phase0 + nbar);   // includes __syncthreads (Ps reuse safe)
    }
}

// ---------------------------------------------------------------
extern "C" void kernel_launch(void* const* d_in, const int* in_sizes, int n_in,
                              void* d_out, int out_size) {
    const float* x    = (const float*)d_in[0];   // [B, T, I]
    const float* Wx   = (const float*)d_in[1];   // [I, 4H]
    const float* Wh   = (const float*)d_in[2];   // [H, 4H]
    const float* bias = (const float*)d_in[3];   // [4H]
    float* out = (float*)d_out;                  // [B, T, H]

    static int smem_set = 0;
    const int smem_bytes = (1024 * 32 + 8 * 64 * 40) * sizeof(float);  // 208 KB
    if (!smem_set) {
        cudaFuncSetAttribute(lstm_persistent_kernel,
                             cudaFuncAttributeMaxDynamicSharedMemorySize, smem_bytes);
        smem_set = 1;
    }

    dim3 g1(G4 / 128, (Bq * Tq) / 128);
    gemm_xproj_kernel<<<g1, 256>>>(x, Wx, bias);

    lstm_persistent_kernel<<<NBLK, 256, smem_bytes>>>(Wh, out);
}

// round 5
// speedup vs baseline: 2.0922x; 2.0367x over previous
#include <cuda_runtime.h>
#include <cuda_bf16.h>
#include <math.h>
#include <stdint.h>

#define Bq 64
#define Tq 512
#define Iq 1024
#define Hq 1024
#define G4 4096          // 4*H
#define KEXP 3072        // 3 * Iq (bf16 split expansion)
#define NBLK 128
#define KC 64

// ---- scratch (static __device__; no allocations allowed) ----
__device__ float g_xproj[(size_t)Tq * Bq * G4];               // [t][b][4H]
__device__ float g_hT[2][Hq * Bq];                            // transposed h
__device__ unsigned g_Aexp[(size_t)(Bq * Tq) * (KEXP / 2)];   // bf16x2 [m][k']
__device__ unsigned g_Bexp[(size_t)G4 * (KEXP / 2)];          // bf16x2 [n][k']

__device__ unsigned g_bar_count = 0;
__device__ volatile unsigned g_bar_phase = 0;

// =============== helpers ===============
__device__ __forceinline__ uint32_t smem_u32(const void* p) {
    uint32_t a;
    asm("{ .reg .u64 t; cvta.to.shared.u64 t, %1; cvt.u32.u64 %0, t; }"
        : "=r"(a) : "l"(p));
    return a;
}

#define CP_ASYNC16(dst, src) \
    asm volatile("cp.async.cg.shared.global [%0], [%1], 16;" :: "r"(dst), "l"(src))
#define CP_COMMIT() asm volatile("cp.async.commit_group;" ::: "memory")
#define CP_WAIT0()  asm volatile("cp.async.wait_group 0;" ::: "memory")

#define LDMX4(r, addr) \
    asm volatile("ldmatrix.sync.aligned.m8n8.x4.shared.b16 {%0,%1,%2,%3}, [%4];" \
        : "=r"((r)[0]), "=r"((r)[1]), "=r"((r)[2]), "=r"((r)[3]) : "r"(addr))

#define MMA16816(c, a, b) \
    asm volatile("mma.sync.aligned.m16n8k16.row.col.f32.bf16.bf16.f32 " \
        "{%0,%1,%2,%3}, {%4,%5,%6,%7}, {%8,%9}, {%0,%1,%2,%3};" \
        : "+f"((c)[0]), "+f"((c)[1]), "+f"((c)[2]), "+f"((c)[3]) \
        : "r"((a)[0]), "r"((a)[1]), "r"((a)[2]), "r"((a)[3]), \
          "r"((b)[0]), "r"((b)[1]))

// =============== split / expand kernels ===============
__device__ __forceinline__ void bf16_split(float v, unsigned& hi, unsigned& lo) {
    __nv_bfloat16 h = __float2bfloat16(v);
    float rem = v - __bfloat162float(h);
    __nv_bfloat16 l = __float2bfloat16(rem);
    hi = (unsigned)__bfloat16_as_ushort(h);
    lo = (unsigned)__bfloat16_as_ushort(l);
}

// A'[m][3k+{0,1,2}] = {ah, ah, al};  x is [b][t][i] = [m][k]
__global__ void split_x_kernel(const float* __restrict__ x) {
    size_t e2 = (size_t)blockIdx.x * 256 + threadIdx.x;   // float2 index
    float2 v = *(const float2*)(x + e2 * 2);
    size_t f0 = e2 * 2;
    size_t m = f0 >> 10;
    int k = (int)(f0 & 1023);
    unsigned h0, l0, h1, l1;
    bf16_split(v.x, h0, l0);
    bf16_split(v.y, h1, l1);
    unsigned* dst = g_Aexp + m * (KEXP / 2) + (size_t)(k >> 1) * 3;
    dst[0] = h0 | (h0 << 16);
    dst[1] = l0 | (h1 << 16);
    dst[2] = h1 | (l1 << 16);
}

// B'[n][3k+{0,1,2}] = {bh, bl, bh};  Wx is [k][n]; B' transposed [n][k']
__global__ void split_w_kernel(const float* __restrict__ Wx) {
    int n = blockIdx.x * 256 + threadIdx.x;
    unsigned* dst = g_Bexp + (size_t)n * (KEXP / 2);
#pragma unroll 4
    for (int k = 0; k < Iq; k += 2) {
        float w0 = Wx[(size_t)k * G4 + n];
        float w1 = Wx[(size_t)(k + 1) * G4 + n];
        unsigned h0, l0, h1, l1;
        bf16_split(w0, h0, l0);
        bf16_split(w1, h1, l1);
        unsigned* d = dst + (k >> 1) * 3;
        d[0] = h0 | (l0 << 16);
        d[1] = h0 | (h1 << 16);
        d[2] = l1 | (h1 << 16);
    }
}

// =============== Phase 1: mma.sync bf16 GEMM  C = A' * B'^T (+bias) ===============
// M=32768, N=4096, K'=3072. CTA tile 128x128, 8 warps (2x4), warp tile 64x32.
// K-chunk 32, double-buffered SMEM via cp.async.
// SMEM tile layout: row-major [128][32] bf16 (64B rows, 4 16B quads),
// quad swizzle q' = q ^ ((row>>1)&3)  -> conflict-free STS16 + ldmatrix.
__global__ void __launch_bounds__(256, 2)
gemm_xproj_mma(const float* __restrict__ bias) {
    __shared__ __align__(1024) unsigned char sm[2][16384];  // [buf]: A@0, B@8192
    const uint32_t smbase = smem_u32(sm);

    const int tid  = threadIdx.x;
    const int wid  = tid >> 5;
    const int lane = tid & 31;
    const int wm   = wid & 1;          // warp row (2 x 64 m)
    const int wn   = wid >> 1;         // warp col (4 x 32 n)

    // supertile mapping: groups of 16 m-tiles x all 32 n-tiles
    int bid = blockIdx.x;
    int gid = bid >> 9;
    int r = bid & 511;
    int mt = gid * 16 + (r & 15);
    int nt = r >> 4;
    const int m0 = mt * 128, n0 = nt * 128;

    // ---- ldmatrix per-lane base addresses (buffer 0, kk=0) ----
    const int gq = lane >> 3;          // matrix index 0..3
    const int rl = lane & 7;
    uint32_t a_addr[4], b_addr[2];
#pragma unroll
    for (int mf = 0; mf < 4; mf++) {
        int row = wm * 64 + mf * 16 + rl + (gq & 1) * 8;
        int q = (gq >> 1) ^ ((row >> 1) & 3);
        a_addr[mf] = smbase + row * 64 + q * 16;
    }
#pragma unroll
    for (int np = 0; np < 2; np++) {
        int row = wn * 32 + np * 16 + rl + (gq & 1) * 8;
        int q = (gq >> 1) ^ ((row >> 1) & 3);
        b_addr[np] = smbase + 8192 + row * 64 + q * 16;
    }

    // ---- cp.async loader ----
    const int4* A4 = (const int4*)g_Aexp;
    const int4* B4 = (const int4*)g_Bexp;
    auto load_chunk = [&](int c, int buf) {
        uint32_t sb = smbase + buf * 16384;
#pragma unroll
        for (int i = 0; i < 2; i++) {
            int u = tid + i * 256;
            int row = u >> 2, q = u & 3;
            uint32_t dst = sb + row * 64 + ((q ^ ((row >> 1) & 3)) << 4);
            CP_ASYNC16(dst, A4 + (size_t)(m0 + row) * 384 + c * 4 + q);
        }
#pragma unroll
        for (int i = 0; i < 2; i++) {
            int u = tid + i * 256;
            int row = u >> 2, q = u & 3;
            uint32_t dst = sb + 8192 + row * 64 + ((q ^ ((row >> 1) & 3)) << 4);
            CP_ASYNC16(dst, B4 + (size_t)(n0 + row) * 384 + c * 4 + q);
        }
    };

    float acc[4][4][4];
#pragma unroll
    for (int mf = 0; mf < 4; mf++)
#pragma unroll
        for (int nf = 0; nf < 4; nf++)
#pragma unroll
            for (int e = 0; e < 4; e++) acc[mf][nf][e] = 0.f;

    load_chunk(0, 0);
    CP_COMMIT();
    CP_WAIT0();
    __syncthreads();

    const int NCH = KEXP / 32;   // 96
    for (int c = 0; c < NCH; c++) {
        if (c + 1 < NCH) { load_chunk(c + 1, (c + 1) & 1); CP_COMMIT(); }

        const uint32_t boff = (c & 1) * 16384u;
#pragma unroll
        for (int kk = 0; kk < 2; kk++) {
            const uint32_t kx = kk << 5;   // XOR 32B flips pre-swizzle quad bit1
            uint32_t a[4][4], b[4][2];
#pragma unroll
            for (int mf = 0; mf < 4; mf++)
                LDMX4(a[mf], (a_addr[mf] + boff) ^ kx);
#pragma unroll
            for (int np = 0; np < 2; np++) {
                uint32_t rr[4];
                LDMX4(rr, (b_addr[np] + boff) ^ kx);
                b[np * 2][0] = rr[0]; b[np * 2][1] = rr[2];
                b[np * 2 + 1][0] = rr[1]; b[np * 2 + 1][1] = rr[3];
            }
#pragma unroll
            for (int mf = 0; mf < 4; mf++)
#pragma unroll
                for (int nf = 0; nf < 4; nf++)
                    MMA16816(acc[mf][nf], a[mf], b[nf]);
        }
        if (c + 1 < NCH) CP_WAIT0();
        __syncthreads();
    }

    // ---- epilogue: bias + write [t][b][4H] ----
#pragma unroll
    for (int mf = 0; mf < 4; mf++) {
        int m = m0 + wm * 64 + mf * 16 + (lane >> 2);
#pragma unroll
        for (int nf = 0; nf < 4; nf++) {
            int n = n0 + wn * 32 + nf * 8 + (lane & 3) * 2;
            float2 bs = *(const float2*)&bias[n];
            {
                int b = m >> 9, t = m & 511;
                size_t idx = ((size_t)t * Bq + b) * G4 + n;
                float2 v = make_float2(acc[mf][nf][0] + bs.x, acc[mf][nf][1] + bs.y);
                *(float2*)&g_xproj[idx] = v;
            }
            {
                int m2 = m + 8;
                int b = m2 >> 9, t = m2 & 511;
                size_t idx = ((size_t)t * Bq + b) * G4 + n;
                float2 v = make_float2(acc[mf][nf][2] + bs.x, acc[mf][nf][3] + bs.y);
                *(float2*)&g_xproj[idx] = v;
            }
        }
    }
}

// =============== grid barrier ===============
__device__ __forceinline__ void grid_sync(unsigned expected) {
    __syncthreads();
    if (threadIdx.x == 0) {
        __threadfence();
        unsigned a = atomicAdd(&g_bar_count, 1u);
        if (a == (unsigned)(gridDim.x - 1)) {
            g_bar_count = 0;
            __threadfence();
            g_bar_phase = expected;
        } else {
            while (g_bar_phase != expected) __nanosleep(64);
        }
        __threadfence();
    }
    __syncthreads();
}

// =============== Phase 2: persistent recurrent kernel (R2 version) ===============
__global__ void __launch_bounds__(256, 1)
lstm_persistent_kernel(const float* __restrict__ Wh, float* __restrict__ out) {
    extern __shared__ float fsm[];
    float* Ws  = fsm;                 // 1024*32
    float* Hs0 = Ws + 1024 * 32;      // 64*64
    float* Hs1 = Hs0 + KC * 64;       // 64*64
    float* Gs  = Hs1 + KC * 64;       // 64*32

    const int tid = threadIdx.x;
    const int tx  = tid & 7;
    const int ty  = tid >> 3;
    const int j0  = blockIdx.x * 8;

    for (int idx = tid; idx < 1024 * 32; idx += 256) {
        int k = idx >> 5, c = idx & 31;
        int col = (c >> 3) * 1024 + j0 + (c & 7);
        Ws[idx] = Wh[(size_t)k * G4 + col];
    }
    for (int idx = tid; idx < 8 * 64; idx += 256)
        g_hT[0][j0 * 64 + idx] = 0.f;

    float creg0 = 0.f, creg1 = 0.f;

    unsigned phase0 = 0;
    if (tid == 0) phase0 = g_bar_phase;
    unsigned nbar = 0;
    nbar++; grid_sync(phase0 + nbar);

    const int gc0 = (tx >> 1) * 1024 + j0 + (tx & 1) * 4;

    for (int t = 0; t < Tq; t++) {
        const float* hT = g_hT[t & 1];
        const float4* hT4 = reinterpret_cast<const float4*>(hT);

        float acc[2][4];
#pragma unroll
        for (int i = 0; i < 2; i++)
#pragma unroll
            for (int q = 0; q < 4; q++) acc[i][q] = 0.f;

        {
            float4* dst = reinterpret_cast<float4*>(Hs0);
#pragma unroll
            for (int i = 0; i < 4; i++) {
                int u = tid + i * 256;
                dst[u] = hT4[u];
            }
        }
        float* cur = Hs0;
        float* nxt = Hs1;

        for (int ch = 0; ch < Hq / KC; ch++) {
            __syncthreads();
            float4 pre[4];
            if (ch < Hq / KC - 1) {
                size_t base4 = (size_t)(ch + 1) * KC * 16;
#pragma unroll
                for (int i = 0; i < 4; i++)
                    pre[i] = hT4[base4 + tid + i * 256];
            }
            const int kbase = ch * KC;
#pragma unroll 16
            for (int kk = 0; kk < KC; kk++) {
                float4 w4 = *reinterpret_cast<const float4*>(&Ws[(kbase + kk) * 32 + tx * 4]);
                float2 h2 = *reinterpret_cast<const float2*>(&cur[kk * 64 + ty * 2]);
                float hv[2] = {h2.x, h2.y};
                float wv[4] = {w4.x, w4.y, w4.z, w4.w};
#pragma unroll
                for (int i = 0; i < 2; i++)
#pragma unroll
                    for (int q = 0; q < 4; q++)
                        acc[i][q] = fmaf(hv[i], wv[q], acc[i][q]);
            }
            if (ch < Hq / KC - 1) {
                float4* dst = reinterpret_cast<float4*>(nxt);
#pragma unroll
                for (int i = 0; i < 4; i++)
                    dst[tid + i * 256] = pre[i];
                float* tmp = cur; cur = nxt; nxt = tmp;
            }
        }

#pragma unroll
        for (int i = 0; i < 2; i++) {
            int b = ty * 2 + i;
            float4 xp = *reinterpret_cast<const float4*>(
                &g_xproj[((size_t)t * Bq + b) * G4 + gc0]);
            float4 v = make_float4(acc[i][0] + xp.x, acc[i][1] + xp.y,
                                   acc[i][2] + xp.z, acc[i][3] + xp.w);
            *reinterpret_cast<float4*>(&Gs[b * 32 + tx * 4]) = v;
        }
        __syncthreads();

        float* hTn = g_hT[(t + 1) & 1];
        {
            int j = tid & 7;
            int b = tid >> 3;
#pragma unroll
            for (int half = 0; half < 2; half++) {
                int bb = b + half * 32;
                float ig = Gs[bb * 32 + 0 * 8 + j];
                float fg = Gs[bb * 32 + 1 * 8 + j];
                float gg = Gs[bb * 32 + 2 * 8 + j];
                float og = Gs[bb * 32 + 3 * 8 + j];
                float iv = 1.f / (1.f + __expf(-ig));
                float fv = 1.f / (1.f + __expf(-fg));
                float gv = tanhf(gg);
                float ov = 1.f / (1.f + __expf(-og));
                float cprev = half ? creg1 : creg0;
                float c = fv * cprev + iv * gv;
                float h = ov * tanhf(c);
                if (half) creg1 = c; else creg0 = c;
                out[((size_t)bb * Tq + t) * Hq + j0 + j] = h;
                hTn[(j0 + j) * 64 + bb] = h;
            }
        }

        nbar++; grid_sync(phase0 + nbar);
    }
}

// ---------------------------------------------------------------
extern "C" void kernel_launch(void* const* d_in, const int* in_sizes, int n_in,
                              void* d_out, int out_size) {
    const float* x    = (const float*)d_in[0];   // [B, T, I]
    const float* Wx   = (const float*)d_in[1];   // [I, 4H]
    const float* Wh   = (const float*)d_in[2];   // [H, 4H]
    const float* bias = (const float*)d_in[3];   // [4H]
    float* out = (float*)d_out;                  // [B, T, H]

    const int rec_smem = (1024 * 32 + 2 * KC * 64 + 64 * 32) * sizeof(float);
    cudaFuncSetAttribute(lstm_persistent_kernel,
                         cudaFuncAttributeMaxDynamicSharedMemorySize, rec_smem);

    split_x_kernel<<<(Bq * Tq * Iq / 2) / 256, 256>>>(x);
    split_w_kernel<<<G4 / 256, 256>>>(Wx);
    gemm_xproj_mma<<<(Bq * Tq / 128) * (G4 / 128), 256>>>(bias);
    lstm_persistent_kernel<<<NBLK, 256, rec_smem>>>(Wh, out);
}

// round 7
// speedup vs baseline: 3.4298x; 1.6393x over previous
#include <cuda_runtime.h>
#include <cuda_bf16.h>
#include <math.h>
#include <stdint.h>

#define Bq 64
#define Tq 512
#define Iq 1024
#define Hq 1024
#define G4 4096          // 4*H
#define KEXP 3072        // 3 * Iq (bf16 split expansion, phase 1)
#define KR 3072          // 3 * Hq (bf16 split expansion, recurrence)
#define NBLK 128

// ---- scratch (static __device__; no allocations allowed) ----
__device__ float g_xproj[(size_t)Tq * Bq * G4];               // [t][b][4H]
__device__ unsigned g_Aexp[(size_t)(Bq * Tq) * (KEXP / 2)];   // bf16x2 [m][k']
__device__ unsigned g_Bexp[(size_t)G4 * (KEXP / 2)];          // bf16x2 [n][k']
__device__ __align__(128) __nv_bfloat16 g_hexp[2][(size_t)KR * Bq]; // h' [k'][64], ping-pong

__device__ unsigned g_bar_count = 0;
__device__ volatile unsigned g_bar_phase = 0;

// =============== helpers ===============
__device__ __forceinline__ uint32_t smem_u32(const void* p) {
    uint32_t a;
    asm("{ .reg .u64 t; cvta.to.shared.u64 t, %1; cvt.u32.u64 %0, t; }"
        : "=r"(a) : "l"(p));
    return a;
}

#define CP_ASYNC16(dst, src) \
    asm volatile("cp.async.cg.shared.global [%0], [%1], 16;" :: "r"(dst), "l"(src))
#define CP_COMMIT() asm volatile("cp.async.commit_group;" ::: "memory")
#define CP_WAIT0()  asm volatile("cp.async.wait_group 0;" ::: "memory")
#define CP_WAIT1()  asm volatile("cp.async.wait_group 1;" ::: "memory")

#define LDMX4(r, addr) \
    asm volatile("ldmatrix.sync.aligned.m8n8.x4.shared.b16 {%0,%1,%2,%3}, [%4];" \
        : "=r"((r)[0]), "=r"((r)[1]), "=r"((r)[2]), "=r"((r)[3]) : "r"(addr))

#define LDMX4T(r, addr) \
    asm volatile("ldmatrix.sync.aligned.m8n8.x4.trans.shared.b16 {%0,%1,%2,%3}, [%4];" \
        : "=r"((r)[0]), "=r"((r)[1]), "=r"((r)[2]), "=r"((r)[3]) : "r"(addr))

#define MMA16816(c, a, b) \
    asm volatile("mma.sync.aligned.m16n8k16.row.col.f32.bf16.bf16.f32 " \
        "{%0,%1,%2,%3}, {%4,%5,%6,%7}, {%8,%9}, {%0,%1,%2,%3};" \
        : "+f"((c)[0]), "+f"((c)[1]), "+f"((c)[2]), "+f"((c)[3]) \
        : "r"((a)[0]), "r"((a)[1]), "r"((a)[2]), "r"((a)[3]), \
          "r"((b)[0]), "r"((b)[1]))

__device__ __forceinline__ void bf16_split(float v, unsigned& hi, unsigned& lo) {
    __nv_bfloat16 h = __float2bfloat16(v);
    float rem = v - __bfloat162float(h);
    __nv_bfloat16 l = __float2bfloat16(rem);
    hi = (unsigned)__bfloat16_as_ushort(h);
    lo = (unsigned)__bfloat16_as_ushort(l);
}

// =============== split / expand kernels (phase 1, unchanged) ===============
__global__ void split_x_kernel(const float* __restrict__ x) {
    size_t e2 = (size_t)blockIdx.x * 256 + threadIdx.x;
    float2 v = *(const float2*)(x + e2 * 2);
    size_t f0 = e2 * 2;
    size_t m = f0 >> 10;
    int k = (int)(f0 & 1023);
    unsigned h0, l0, h1, l1;
    bf16_split(v.x, h0, l0);
    bf16_split(v.y, h1, l1);
    unsigned* dst = g_Aexp + m * (KEXP / 2) + (size_t)(k >> 1) * 3;
    dst[0] = h0 | (h0 << 16);
    dst[1] = l0 | (h1 << 16);
    dst[2] = h1 | (l1 << 16);
}

__global__ void split_w_kernel(const float* __restrict__ Wx) {
    int n = blockIdx.x * 256 + threadIdx.x;
    unsigned* dst = g_Bexp + (size_t)n * (KEXP / 2);
#pragma unroll 4
    for (int k = 0; k < Iq; k += 2) {
        float w0 = Wx[(size_t)k * G4 + n];
        float w1 = Wx[(size_t)(k + 1) * G4 + n];
        unsigned h0, l0, h1, l1;
        bf16_split(w0, h0, l0);
        bf16_split(w1, h1, l1);
        unsigned* d = dst + (k >> 1) * 3;
        d[0] = h0 | (l0 << 16);
        d[1] = h0 | (h1 << 16);
        d[2] = l1 | (h1 << 16);
    }
}

// =============== Phase 1: mma.sync bf16 GEMM (unchanged from R5) ===============
__global__ void __launch_bounds__(256, 2)
gemm_xproj_mma(const float* __restrict__ bias) {
    __shared__ __align__(1024) unsigned char sm[2][16384];
    const uint32_t smbase = smem_u32(sm);

    const int tid  = threadIdx.x;
    const int wid  = tid >> 5;
    const int lane = tid & 31;
    const int wm   = wid & 1;
    const int wn   = wid >> 1;

    int bid = blockIdx.x;
    int gid = bid >> 9;
    int r = bid & 511;
    int mt = gid * 16 + (r & 15);
    int nt = r >> 4;
    const int m0 = mt * 128, n0 = nt * 128;

    const int gq = lane >> 3;
    const int rl = lane & 7;
    uint32_t a_addr[4], b_addr[2];
#pragma unroll
    for (int mf = 0; mf < 4; mf++) {
        int row = wm * 64 + mf * 16 + rl + (gq & 1) * 8;
        int q = (gq >> 1) ^ ((row >> 1) & 3);
        a_addr[mf] = smbase + row * 64 + q * 16;
    }
#pragma unroll
    for (int np = 0; np < 2; np++) {
        int row = wn * 32 + np * 16 + rl + (gq & 1) * 8;
        int q = (gq >> 1) ^ ((row >> 1) & 3);
        b_addr[np] = smbase + 8192 + row * 64 + q * 16;
    }

    const int4* A4 = (const int4*)g_Aexp;
    const int4* B4 = (const int4*)g_Bexp;
    auto load_chunk = [&](int c, int buf) {
        uint32_t sb = smbase + buf * 16384;
#pragma unroll
        for (int i = 0; i < 2; i++) {
            int u = tid + i * 256;
            int row = u >> 2, q = u & 3;
            uint32_t dst = sb + row * 64 + ((q ^ ((row >> 1) & 3)) << 4);
            CP_ASYNC16(dst, A4 + (size_t)(m0 + row) * 384 + c * 4 + q);
        }
#pragma unroll
        for (int i = 0; i < 2; i++) {
            int u = tid + i * 256;
            int row = u >> 2, q = u & 3;
            uint32_t dst = sb + 8192 + row * 64 + ((q ^ ((row >> 1) & 3)) << 4);
            CP_ASYNC16(dst, B4 + (size_t)(n0 + row) * 384 + c * 4 + q);
        }
    };

    float acc[4][4][4];
#pragma unroll
    for (int mf = 0; mf < 4; mf++)
#pragma unroll
        for (int nf = 0; nf < 4; nf++)
#pragma unroll
            for (int e = 0; e < 4; e++) acc[mf][nf][e] = 0.f;

    load_chunk(0, 0);
    CP_COMMIT();
    CP_WAIT0();
    __syncthreads();

    const int NCH = KEXP / 32;
    for (int c = 0; c < NCH; c++) {
        if (c + 1 < NCH) { load_chunk(c + 1, (c + 1) & 1); CP_COMMIT(); }

        const uint32_t boff = (c & 1) * 16384u;
#pragma unroll
        for (int kk = 0; kk < 2; kk++) {
            const uint32_t kx = kk << 5;
            uint32_t a[4][4], b[4][2];
#pragma unroll
            for (int mf = 0; mf < 4; mf++)
                LDMX4(a[mf], (a_addr[mf] + boff) ^ kx);
#pragma unroll
            for (int np = 0; np < 2; np++) {
                uint32_t rr[4];
                LDMX4(rr, (b_addr[np] + boff) ^ kx);
                b[np * 2][0] = rr[0]; b[np * 2][1] = rr[2];
                b[np * 2 + 1][0] = rr[1]; b[np * 2 + 1][1] = rr[3];
            }
#pragma unroll
            for (int mf = 0; mf < 4; mf++)
#pragma unroll
                for (int nf = 0; nf < 4; nf++)
                    MMA16816(acc[mf][nf], a[mf], b[nf]);
        }
        if (c + 1 < NCH) CP_WAIT0();
        __syncthreads();
    }

#pragma unroll
    for (int mf = 0; mf < 4; mf++) {
        int m = m0 + wm * 64 + mf * 16 + (lane >> 2);
#pragma unroll
        for (int nf = 0; nf < 4; nf++) {
            int n = n0 + wn * 32 + nf * 8 + (lane & 3) * 2;
            float2 bs = *(const float2*)&bias[n];
            {
                int b = m >> 9, t = m & 511;
                size_t idx = ((size_t)t * Bq + b) * G4 + n;
                float2 v = make_float2(acc[mf][nf][0] + bs.x, acc[mf][nf][1] + bs.y);
                *(float2*)&g_xproj[idx] = v;
            }
            {
                int m2 = m + 8;
                int b = m2 >> 9, t = m2 & 511;
                size_t idx = ((size_t)t * Bq + b) * G4 + n;
                float2 v = make_float2(acc[mf][nf][2] + bs.x, acc[mf][nf][3] + bs.y);
                *(float2*)&g_xproj[idx] = v;
            }
        }
    }
}

// =============== grid barrier ===============
__device__ __forceinline__ void grid_sync(unsigned expected) {
    __syncthreads();
    if (threadIdx.x == 0) {
        __threadfence();
        unsigned a = atomicAdd(&g_bar_count, 1u);
        if (a == (unsigned)(gridDim.x - 1)) {
            g_bar_count = 0;
            __threadfence();
            g_bar_phase = expected;
        } else {
            while (g_bar_phase != expected) __nanosleep(64);
        }
        __threadfence();
    }
    __syncthreads();
}

// =============== Phase 2: tensor-core persistent recurrence ===============
// Block bx owns h-cols j0..j0+7 -> gate cols n (row n = g*8+jj -> col g*1024+j0+jj).
// SMEM: Bs[32][3072] bf16 split-Wh slice (192KB, built once) +
//       As dbl buf [128][64] bf16 chunks of h' (2x16KB).
// Warps 0-3: MMA m16 x n32 x K'=3072 each. Warps 4-7: cp.async h' chunks.
// Swizzles: 16B-chunk index XOR'd with (row&7) in both tiles.
__global__ void __launch_bounds__(256, 1)
lstm_tc_kernel(const float* __restrict__ Wh, float* __restrict__ out) {
    extern __shared__ __align__(128) char sm2[];
    char* BsC = sm2;                    // 32 * 6144 = 196608
    char* AsC = sm2 + 196608;           // 2 * 16384 = 32768
    const uint32_t Bsb = smem_u32(BsC);
    const uint32_t Asb = smem_u32(AsC);

    const int tid  = threadIdx.x;
    const int wid  = tid >> 5;
    const int lane = tid & 31;
    const int j0   = blockIdx.x * 8;
    const bool is_mma = (wid < 4);

    // ---- build split-Wh slice in SMEM (once) ----
    for (int idx = tid; idx < 32 * 1024; idx += 256) {
        int n = idx & 31;
        int k = idx >> 5;
        int g = n >> 3, jj = n & 7;
        float w = Wh[(size_t)k * G4 + g * 1024 + j0 + jj];
        unsigned bh, bl;
        bf16_split(w, bh, bl);
        // k' = 3k:{bh}, 3k+1:{bl}, 3k+2:{bh}
#pragma unroll
        for (int r = 0; r < 3; r++) {
            unsigned v = (r == 1) ? bl : bh;
            uint32_t kb = (3 * k + r) * 2;
            uint32_t chunk = kb >> 4, off = kb & 15;
            *(unsigned short*)(BsC + n * 6144 + ((chunk ^ (n & 7)) << 4) + off) =
                (unsigned short)v;
        }
    }

    // ---- zero my rows of h'[0] ----
    {
        __nv_bfloat16* hz = g_hexp[0] + (size_t)(3 * j0) * 64;
        for (int idx = tid; idx < 24 * 64; idx += 256)
            hz[idx] = __ushort_as_bfloat16(0);
    }

    // ---- per-thread MMA constants ----
    const int gq = lane >> 3, rl = lane & 7;
    // A: [k][64] rows of 128B; warp wid owns m16 = cols [wid*16, wid*16+16)
    const uint32_t a_off = (uint32_t)((rl + ((gq >> 1) << 3)) * 128 +
                           ((wid * 32 + (gq & 1) * 16) ^ (rl << 4)));
    // B: rows n, 6144B stride
    uint32_t b_row_off[2];
#pragma unroll
    for (int nh = 0; nh < 2; nh++)
        b_row_off[nh] = (uint32_t)((nh * 16 + rl + (gq & 1) * 8) * 6144);
    const uint32_t b_swz = (uint32_t)rl;     // (row & 7) == rl for both halves
    const uint32_t gqk = (uint32_t)(gq >> 1);

    float acc[4][4];
#pragma unroll
    for (int g = 0; g < 4; g++)
#pragma unroll
        for (int e = 0; e < 4; e++) acc[g][e] = 0.f;
    float cst[4] = {0.f, 0.f, 0.f, 0.f};

    // pointwise combo mapping (MMA warps)
    const int pb0 = wid * 16 + (lane >> 2);
    const int pjj0 = (lane & 3) * 2;

    unsigned phase0 = 0;
    if (tid == 0) phase0 = g_bar_phase;
    unsigned nbar = 0;
    nbar++; grid_sync(phase0 + nbar);     // Bs + h'[0] visible

    const int htid = tid - 128;           // helper index 0..127

    for (int t = 0; t < Tq; t++) {
        const __nv_bfloat16* Asrc = g_hexp[t & 1];

        // helper: preload chunk 0
        if (!is_mma) {
#pragma unroll
            for (int i = 0; i < 8; i++) {
                int u = htid + i * 128;
                int krow = u >> 3, q = u & 7;
                uint32_t dst = Asb + krow * 128 + (((uint32_t)q ^ (krow & 7)) << 4);
                CP_ASYNC16(dst, Asrc + (size_t)krow * 64 + q * 8);
            }
            CP_COMMIT();
        }

        for (int ch = 0; ch < 24; ch++) {
            if (!is_mma) {
                if (ch + 1 < 24) {
                    uint32_t sb = Asb + ((ch + 1) & 1) * 16384;
                    const __nv_bfloat16* src = Asrc + (size_t)(ch + 1) * 128 * 64;
#pragma unroll
                    for (int i = 0; i < 8; i++) {
                        int u = htid + i * 128;
                        int krow = u >> 3, q = u & 7;
                        uint32_t dst = sb + krow * 128 + (((uint32_t)q ^ (krow & 7)) << 4);
                        CP_ASYNC16(dst, src + (size_t)krow * 64 + q * 8);
                    }
                    CP_COMMIT();
                    CP_WAIT1();
                } else {
                    CP_WAIT0();
                }
            }
            __syncthreads();    // chunk ch visible

            if (is_mma) {
                const uint32_t abase = Asb + (ch & 1) * 16384 + a_off;
                const uint32_t kc0 = (uint32_t)(ch * 16);
#pragma unroll
                for (int kk = 0; kk < 8; kk++) {
                    uint32_t a[4];
                    LDMX4T(a, abase + kk * 2048);
                    uint32_t b[4][2];
#pragma unroll
                    for (int nh = 0; nh < 2; nh++) {
                        uint32_t rr[4];
                        uint32_t chunk = ((kc0 + kk * 2) | gqk) ^ b_swz;
                        LDMX4(rr, Bsb + b_row_off[nh] + (chunk << 4));
                        b[nh * 2][0] = rr[0]; b[nh * 2][1] = rr[2];
                        b[nh * 2 + 1][0] = rr[1]; b[nh * 2 + 1][1] = rr[3];
                    }
#pragma unroll
                    for (int g = 0; g < 4; g++)
                        MMA16816(acc[g], a, b[g]);
                }
            }
            __syncthreads();    // MMA done with buf ch&1 (reused at ch+2)
        }

        // ---- pointwise (MMA warps only) ----
        if (is_mma) {
            __nv_bfloat16* hn = g_hexp[(t + 1) & 1];
#pragma unroll
            for (int ci = 0; ci < 4; ci++) {
                int b  = (ci < 2) ? pb0 : pb0 + 8;
                int jj = (ci & 1) ? pjj0 + 1 : pjj0;
                size_t xb = ((size_t)t * Bq + b) * G4 + j0 + jj;
                float ig = acc[0][ci] + g_xproj[xb];
                float fg = acc[1][ci] + g_xproj[xb + 1024];
                float gg = acc[2][ci] + g_xproj[xb + 2048];
                float og = acc[3][ci] + g_xproj[xb + 3072];

                float iv = 1.f / (1.f + __expf(-ig));
                float fv = 1.f / (1.f + __expf(-fg));
                float gv = tanhf(gg);
                float ov = 1.f / (1.f + __expf(-og));

                float c = fv * cst[ci] + iv * gv;
                float h = ov * tanhf(c);
                cst[ci] = c;

                out[((size_t)b * Tq + t) * Hq + j0 + jj] = h;

                __nv_bfloat16 ah = __float2bfloat16(h);
                float rem = h - __bfloat162float(ah);
                __nv_bfloat16 al = __float2bfloat16(rem);
                size_t rbase = (size_t)(3 * (j0 + jj)) * 64 + b;
                hn[rbase]           = ah;
                hn[rbase + 64]      = ah;
                hn[rbase + 128]     = al;

                acc[0][ci] = 0.f; acc[1][ci] = 0.f;
                acc[2][ci] = 0.f; acc[3][ci] = 0.f;
            }
        }

        nbar++; grid_sync(phase0 + nbar);
    }
}

// ---------------------------------------------------------------
extern "C" void kernel_launch(void* const* d_in, const int* in_sizes, int n_in,
                              void* d_out, int out_size) {
    const float* x    = (const float*)d_in[0];   // [B, T, I]
    const float* Wx   = (const float*)d_in[1];   // [I, 4H]
    const float* Wh   = (const float*)d_in[2];   // [H, 4H]
    const float* bias = (const float*)d_in[3];   // [4H]
    float* out = (float*)d_out;                  // [B, T, H]

    const int rec_smem = 196608 + 32768;         // 224 KB
    cudaFuncSetAttribute(lstm_tc_kernel,
                         cudaFuncAttributeMaxDynamicSharedMemorySize, rec_smem);

    split_x_kernel<<<(Bq * Tq * Iq / 2) / 256, 256>>>(x);
    split_w_kernel<<<G4 / 256, 256>>>(Wx);
    gemm_xproj_mma<<<(Bq * Tq / 128) * (G4 / 128), 256>>>(bias);
    lstm_tc_kernel<<<NBLK, 256, rec_smem>>>(Wh, out);
}

// round 8
// speedup vs baseline: 4.2359x; 1.2350x over previous
#include <cuda_runtime.h>
#include <cuda_bf16.h>
#include <math.h>
#include <stdint.h>

#define Bq 64
#define Tq 512
#define Iq 1024
#define Hq 1024
#define G4 4096          // 4*H
#define KEXP 3072        // 3 * Iq (phase-1 split, interleaved)
#define KR2 2048         // 2 * Hq (phase-2 split, segmented [ah|al])
#define NBLK 128

// ---- scratch (static __device__; no allocations allowed) ----
__device__ float g_xproj[(size_t)Tq * Bq * G4];               // [t][b][4H]
__device__ unsigned g_Aexp[(size_t)(Bq * Tq) * (KEXP / 2)];   // bf16x2 [m][k']
__device__ unsigned g_Bexp[(size_t)G4 * (KEXP / 2)];          // bf16x2 [n][k']
__device__ __align__(128) __nv_bfloat16 g_hexp[2][(size_t)KR2 * Bq]; // h' [k'][64]

__device__ unsigned g_bar_count = 0;
__device__ volatile unsigned g_bar_phase = 0;

// =============== helpers ===============
__device__ __forceinline__ uint32_t smem_u32(const void* p) {
    uint32_t a;
    asm("{ .reg .u64 t; cvta.to.shared.u64 t, %1; cvt.u32.u64 %0, t; }"
        : "=r"(a) : "l"(p));
    return a;
}

#define CP_ASYNC16(dst, src) \
    asm volatile("cp.async.cg.shared.global [%0], [%1], 16;" :: "r"(dst), "l"(src))
#define CP_COMMIT() asm volatile("cp.async.commit_group;" ::: "memory")
#define CP_WAIT0()  asm volatile("cp.async.wait_group 0;" ::: "memory")
#define CP_WAIT1()  asm volatile("cp.async.wait_group 1;" ::: "memory")
#define CP_WAIT2()  asm volatile("cp.async.wait_group 2;" ::: "memory")

#define BAR_SYNC_N(id)   asm volatile("bar.sync %0, 256;"   :: "r"(id) : "memory")
#define BAR_ARRIVE_N(id) asm volatile("bar.arrive %0, 256;" :: "r"(id) : "memory")

#define LDMX4(r, addr) \
    asm volatile("ldmatrix.sync.aligned.m8n8.x4.shared.b16 {%0,%1,%2,%3}, [%4];" \
        : "=r"((r)[0]), "=r"((r)[1]), "=r"((r)[2]), "=r"((r)[3]) : "r"(addr))

#define LDMX4T(r, addr) \
    asm volatile("ldmatrix.sync.aligned.m8n8.x4.trans.shared.b16 {%0,%1,%2,%3}, [%4];" \
        : "=r"((r)[0]), "=r"((r)[1]), "=r"((r)[2]), "=r"((r)[3]) : "r"(addr))

#define MMA16816(c, a, b) \
    asm volatile("mma.sync.aligned.m16n8k16.row.col.f32.bf16.bf16.f32 " \
        "{%0,%1,%2,%3}, {%4,%5,%6,%7}, {%8,%9}, {%0,%1,%2,%3};" \
        : "+f"((c)[0]), "+f"((c)[1]), "+f"((c)[2]), "+f"((c)[3]) \
        : "r"((a)[0]), "r"((a)[1]), "r"((a)[2]), "r"((a)[3]), \
          "r"((b)[0]), "r"((b)[1]))

__device__ __forceinline__ void bf16_split(float v, unsigned& hi, unsigned& lo) {
    __nv_bfloat16 h = __float2bfloat16(v);
    float rem = v - __bfloat162float(h);
    __nv_bfloat16 l = __float2bfloat16(rem);
    hi = (unsigned)__bfloat16_as_ushort(h);
    lo = (unsigned)__bfloat16_as_ushort(l);
}

// =============== split / expand kernels (phase 1, unchanged) ===============
__global__ void split_x_kernel(const float* __restrict__ x) {
    size_t e2 = (size_t)blockIdx.x * 256 + threadIdx.x;
    float2 v = *(const float2*)(x + e2 * 2);
    size_t f0 = e2 * 2;
    size_t m = f0 >> 10;
    int k = (int)(f0 & 1023);
    unsigned h0, l0, h1, l1;
    bf16_split(v.x, h0, l0);
    bf16_split(v.y, h1, l1);
    unsigned* dst = g_Aexp + m * (KEXP / 2) + (size_t)(k >> 1) * 3;
    dst[0] = h0 | (h0 << 16);
    dst[1] = l0 | (h1 << 16);
    dst[2] = h1 | (l1 << 16);
}

__global__ void split_w_kernel(const float* __restrict__ Wx) {
    int n = blockIdx.x * 256 + threadIdx.x;
    unsigned* dst = g_Bexp + (size_t)n * (KEXP / 2);
#pragma unroll 4
    for (int k = 0; k < Iq; k += 2) {
        float w0 = Wx[(size_t)k * G4 + n];
        float w1 = Wx[(size_t)(k + 1) * G4 + n];
        unsigned h0, l0, h1, l1;
        bf16_split(w0, h0, l0);
        bf16_split(w1, h1, l1);
        unsigned* d = dst + (k >> 1) * 3;
        d[0] = h0 | (l0 << 16);
        d[1] = h0 | (h1 << 16);
        d[2] = l1 | (h1 << 16);
    }
}

// =============== Phase 1: mma.sync bf16 GEMM (unchanged from R5) ===============
__global__ void __launch_bounds__(256, 2)
gemm_xproj_mma(const float* __restrict__ bias) {
    __shared__ __align__(1024) unsigned char sm[2][16384];
    const uint32_t smbase = smem_u32(sm);

    const int tid  = threadIdx.x;
    const int wid  = tid >> 5;
    const int lane = tid & 31;
    const int wm   = wid & 1;
    const int wn   = wid >> 1;

    int bid = blockIdx.x;
    int gid = bid >> 9;
    int r = bid & 511;
    int mt = gid * 16 + (r & 15);
    int nt = r >> 4;
    const int m0 = mt * 128, n0 = nt * 128;

    const int gq = lane >> 3;
    const int rl = lane & 7;
    uint32_t a_addr[4], b_addr[2];
#pragma unroll
    for (int mf = 0; mf < 4; mf++) {
        int row = wm * 64 + mf * 16 + rl + (gq & 1) * 8;
        int q = (gq >> 1) ^ ((row >> 1) & 3);
        a_addr[mf] = smbase + row * 64 + q * 16;
    }
#pragma unroll
    for (int np = 0; np < 2; np++) {
        int row = wn * 32 + np * 16 + rl + (gq & 1) * 8;
        int q = (gq >> 1) ^ ((row >> 1) & 3);
        b_addr[np] = smbase + 8192 + row * 64 + q * 16;
    }

    const int4* A4 = (const int4*)g_Aexp;
    const int4* B4 = (const int4*)g_Bexp;
    auto load_chunk = [&](int c, int buf) {
        uint32_t sb = smbase + buf * 16384;
#pragma unroll
        for (int i = 0; i < 2; i++) {
            int u = tid + i * 256;
            int row = u >> 2, q = u & 3;
            uint32_t dst = sb + row * 64 + ((q ^ ((row >> 1) & 3)) << 4);
            CP_ASYNC16(dst, A4 + (size_t)(m0 + row) * 384 + c * 4 + q);
        }
#pragma unroll
        for (int i = 0; i < 2; i++) {
            int u = tid + i * 256;
            int row = u >> 2, q = u & 3;
            uint32_t dst = sb + 8192 + row * 64 + ((q ^ ((row >> 1) & 3)) << 4);
            CP_ASYNC16(dst, B4 + (size_t)(n0 + row) * 384 + c * 4 + q);
        }
    };

    float acc[4][4][4];
#pragma unroll
    for (int mf = 0; mf < 4; mf++)
#pragma unroll
        for (int nf = 0; nf < 4; nf++)
#pragma unroll
            for (int e = 0; e < 4; e++) acc[mf][nf][e] = 0.f;

    load_chunk(0, 0);
    CP_COMMIT();
    CP_WAIT0();
    __syncthreads();

    const int NCH = KEXP / 32;
    for (int c = 0; c < NCH; c++) {
        if (c + 1 < NCH) { load_chunk(c + 1, (c + 1) & 1); CP_COMMIT(); }

        const uint32_t boff = (c & 1) * 16384u;
#pragma unroll
        for (int kk = 0; kk < 2; kk++) {
            const uint32_t kx = kk << 5;
            uint32_t a[4][4], b[4][2];
#pragma unroll
            for (int mf = 0; mf < 4; mf++)
                LDMX4(a[mf], (a_addr[mf] + boff) ^ kx);
#pragma unroll
            for (int np = 0; np < 2; np++) {
                uint32_t rr[4];
                LDMX4(rr, (b_addr[np] + boff) ^ kx);
                b[np * 2][0] = rr[0]; b[np * 2][1] = rr[2];
                b[np * 2 + 1][0] = rr[1]; b[np * 2 + 1][1] = rr[3];
            }
#pragma unroll
            for (int mf = 0; mf < 4; mf++)
#pragma unroll
                for (int nf = 0; nf < 4; nf++)
                    MMA16816(acc[mf][nf], a[mf], b[nf]);
        }
        if (c + 1 < NCH) CP_WAIT0();
        __syncthreads();
    }

#pragma unroll
    for (int mf = 0; mf < 4; mf++) {
        int m = m0 + wm * 64 + mf * 16 + (lane >> 2);
#pragma unroll
        for (int nf = 0; nf < 4; nf++) {
            int n = n0 + wn * 32 + nf * 8 + (lane & 3) * 2;
            float2 bs = *(const float2*)&bias[n];
            {
                int b = m >> 9, t = m & 511;
                size_t idx = ((size_t)t * Bq + b) * G4 + n;
                float2 v = make_float2(acc[mf][nf][0] + bs.x, acc[mf][nf][1] + bs.y);
                *(float2*)&g_xproj[idx] = v;
            }
            {
                int m2 = m + 8;
                int b = m2 >> 9, t = m2 & 511;
                size_t idx = ((size_t)t * Bq + b) * G4 + n;
                float2 v = make_float2(acc[mf][nf][2] + bs.x, acc[mf][nf][3] + bs.y);
                *(float2*)&g_xproj[idx] = v;
            }
        }
    }
}

// =============== grid barrier ===============
__device__ __forceinline__ void grid_sync(unsigned expected) {
    __syncthreads();
    if (threadIdx.x == 0) {
        __threadfence();
        unsigned a = atomicAdd(&g_bar_count, 1u);
        if (a == (unsigned)(gridDim.x - 1)) {
            g_bar_count = 0;
            __threadfence();
            g_bar_phase = expected;
        } else {
            while (g_bar_phase != expected) __nanosleep(64);
        }
        __threadfence();
    }
    __syncthreads();
}

// =============== Phase 2: tensor-core persistent recurrence (v2) ===============
// K-split segmented: A' = [ah(1024) | al(1024)]  (K'=2048, g_hexp).
//   gates = sum_ah(ah x bh + ah x bl) + sum_al(al x bh)
// SMEM: BH [32 n][1024 k'] @0 (64KB), BL @64KB (64KB), A bufs 4 x 16KB @128KB.
// Warps 0-3: MMA m16 x n32; warps 4-7: cp.async producers.
// Named barriers: RDY(buf)=1..4, FREE(buf)=5..8, count 256 (128 sync + 128 arrive).
__global__ void __launch_bounds__(256, 1)
lstm_tc_kernel(const float* __restrict__ Wh, float* __restrict__ out) {
    extern __shared__ __align__(128) char sm2[];
    const uint32_t Bsb = smem_u32(sm2);
    const uint32_t Asb = Bsb + 131072u;

    const int tid  = threadIdx.x;
    const int wid  = tid >> 5;
    const int lane = tid & 31;
    const int j0   = blockIdx.x * 8;
    const bool is_mma = (wid < 4);

    // ---- build split-Wh slices BH / BL (once) ----
    for (int idx = tid; idx < 32 * 1024; idx += 256) {
        int n = idx & 31;
        int k = idx >> 5;
        int g = n >> 3, jj = n & 7;
        float w = Wh[(size_t)k * G4 + g * 1024 + j0 + jj];
        unsigned bh, bl;
        bf16_split(w, bh, bl);
        uint32_t base = (uint32_t)(n * 2048 + (((k >> 3) ^ (n & 7)) << 4) + (k & 7) * 2);
        *(unsigned short*)(sm2 + base)          = (unsigned short)bh;
        *(unsigned short*)(sm2 + 65536u + base) = (unsigned short)bl;
    }

    // ---- zero my rows of h'[0]: seg0 rows j0..j0+7, seg1 rows 1024+j0.. ----
    {
        __nv_bfloat16* hz = g_hexp[0];
        for (int idx = tid; idx < 16 * 64; idx += 256) {
            int r = idx >> 6;
            int row = (r < 8) ? (j0 + r) : (1024 + j0 + (r - 8));
            hz[(size_t)row * 64 + (idx & 63)] = __ushort_as_bfloat16(0);
        }
    }

    // ---- per-thread MMA constants ----
    const int gq = lane >> 3, rl = lane & 7;
    const uint32_t a_off = (uint32_t)((rl + ((gq >> 1) << 3)) * 128 +
                           ((wid * 32 + (gq & 1) * 16) ^ (rl << 4)));
    uint32_t b_row_off[2];
#pragma unroll
    for (int nh = 0; nh < 2; nh++)
        b_row_off[nh] = (uint32_t)((nh * 16 + rl + (gq & 1) * 8) * 2048);
    const uint32_t gqk = (uint32_t)(gq >> 1);
    const uint32_t bswz = (uint32_t)rl;

    float acc[4][4];
#pragma unroll
    for (int g = 0; g < 4; g++)
#pragma unroll
        for (int e = 0; e < 4; e++) acc[g][e] = 0.f;
    float cst[4] = {0.f, 0.f, 0.f, 0.f};

    const int pb0 = wid * 16 + (lane >> 2);
    const int pjj0 = (lane & 3) * 2;

    unsigned phase0 = 0;
    if (tid == 0) phase0 = g_bar_phase;
    unsigned nbar = 0;
    nbar++; grid_sync(phase0 + nbar);     // BH/BL + h'[0] visible

    const int htid = tid - 128;

    // xproj prefetch regs (consumers)
    float2 xp[2][4];
    if (is_mma) {
#pragma unroll
        for (int hb = 0; hb < 2; hb++) {
            int b = pb0 + hb * 8;
            size_t base = ((size_t)0 * Bq + b) * G4 + j0 + pjj0;
#pragma unroll
            for (int g = 0; g < 4; g++)
                xp[hb][g] = *(const float2*)&g_xproj[base + g * 1024];
        }
    }

    for (int t = 0; t < Tq; t++) {
        if (!is_mma) {
            // ================= producer =================
            const __nv_bfloat16* Asrc = g_hexp[t & 1];
            for (int ch = 0; ch < 16; ch++) {
                if (!(t == 0 && ch < 4)) BAR_SYNC_N(5 + (ch & 3));
                uint32_t sbuf = Asb + (uint32_t)(ch & 3) * 16384u;
                const __nv_bfloat16* src = Asrc + (size_t)ch * 8192;
#pragma unroll
                for (int i = 0; i < 8; i++) {
                    int u = htid + i * 128;
                    int krow = u >> 3, q = u & 7;
                    uint32_t dst = sbuf + krow * 128 + (((uint32_t)q ^ (krow & 7)) << 4);
                    CP_ASYNC16(dst, src + (size_t)krow * 64 + q * 8);
                }
                CP_COMMIT();
                if (ch >= 2) { CP_WAIT2(); BAR_ARRIVE_N(1 + ((ch - 2) & 3)); }
            }
            CP_WAIT1(); BAR_ARRIVE_N(1 + 2);
            CP_WAIT0(); BAR_ARRIVE_N(1 + 3);
        } else {
            // ================= consumer =================
            for (int ch = 0; ch < 16; ch++) {
                BAR_SYNC_N(1 + (ch & 3));
                const uint32_t abase = Asb + (uint32_t)(ch & 3) * 16384u + a_off;
                const uint32_t kc0 = (uint32_t)((ch & 7) * 16);
                if (ch < 8) {
                    // ah chunk: vs BH and BL
#pragma unroll
                    for (int kk = 0; kk < 8; kk++) {
                        uint32_t a[4];
                        LDMX4T(a, abase + kk * 2048);
                        uint32_t cidx = ((kc0 + kk * 2) | gqk) ^ bswz;
                        uint32_t bH[4][2], bL[4][2];
#pragma unroll
                        for (int nh = 0; nh < 2; nh++) {
                            uint32_t rr[4];
                            LDMX4(rr, Bsb + b_row_off[nh] + (cidx << 4));
                            bH[nh * 2][0] = rr[0]; bH[nh * 2][1] = rr[2];
                            bH[nh * 2 + 1][0] = rr[1]; bH[nh * 2 + 1][1] = rr[3];
                            LDMX4(rr, Bsb + 65536u + b_row_off[nh] + (cidx << 4));
                            bL[nh * 2][0] = rr[0]; bL[nh * 2][1] = rr[2];
                            bL[nh * 2 + 1][0] = rr[1]; bL[nh * 2 + 1][1] = rr[3];
                        }
#pragma unroll
                        for (int g = 0; g < 4; g++) MMA16816(acc[g], a, bH[g]);
#pragma unroll
                        for (int g = 0; g < 4; g++) MMA16816(acc[g], a, bL[g]);
                    }
                } else {
                    // al chunk: vs BH only
#pragma unroll
                    for (int kk = 0; kk < 8; kk++) {
                        uint32_t a[4];
                        LDMX4T(a, abase + kk * 2048);
                        uint32_t cidx = ((kc0 + kk * 2) | gqk) ^ bswz;
                        uint32_t bH[4][2];
#pragma unroll
                        for (int nh = 0; nh < 2; nh++) {
                            uint32_t rr[4];
                            LDMX4(rr, Bsb + b_row_off[nh] + (cidx << 4));
                            bH[nh * 2][0] = rr[0]; bH[nh * 2][1] = rr[2];
                            bH[nh * 2 + 1][0] = rr[1]; bH[nh * 2 + 1][1] = rr[3];
                        }
#pragma unroll
                        for (int g = 0; g < 4; g++) MMA16816(acc[g], a, bH[g]);
                    }
                }
                BAR_ARRIVE_N(5 + (ch & 3));
            }

            // ---- pointwise: gates -> c,h; write out + h' ----
            __nv_bfloat16* hn = g_hexp[(t + 1) & 1];
#pragma unroll
            for (int ci = 0; ci < 4; ci++) {
                int hb = ci >> 1;
                int b  = pb0 + hb * 8;
                int jj = pjj0 + (ci & 1);
                float ig = acc[0][ci] + ((ci & 1) ? xp[hb][0].y : xp[hb][0].x);
                float fg = acc[1][ci] + ((ci & 1) ? xp[hb][1].y : xp[hb][1].x);
                float gg = acc[2][ci] + ((ci & 1) ? xp[hb][2].y : xp[hb][2].x);
                float og = acc[3][ci] + ((ci & 1) ? xp[hb][3].y : xp[hb][3].x);

                float iv = 1.f / (1.f + __expf(-ig));
                float fv = 1.f / (1.f + __expf(-fg));
                float gv = tanhf(gg);
                float ov = 1.f / (1.f + __expf(-og));

                float c = fv * cst[ci] + iv * gv;
                float h = ov * tanhf(c);
                cst[ci] = c;

                out[((size_t)b * Tq + t) * Hq + j0 + jj] = h;

                __nv_bfloat16 ah = __float2bfloat16(h);
                float rem = h - __bfloat162float(ah);
                __nv_bfloat16 al = __float2bfloat16(rem);
                hn[(size_t)(j0 + jj) * 64 + b]          = ah;
                hn[(size_t)(1024 + j0 + jj) * 64 + b]   = al;

                acc[0][ci] = 0.f; acc[1][ci] = 0.f;
                acc[2][ci] = 0.f; acc[3][ci] = 0.f;
            }

            // ---- prefetch xproj for next step (hidden behind grid_sync) ----
            {
                int tn = (t + 1 < Tq) ? t + 1 : t;
#pragma unroll
                for (int hb = 0; hb < 2; hb++) {
                    int b = pb0 + hb * 8;
                    size_t base = ((size_t)tn * Bq + b) * G4 + j0 + pjj0;
#pragma unroll
                    for (int g = 0; g < 4; g++)
                        xp[hb][g] = *(const float2*)&g_xproj[base + g * 1024];
                }
            }
        }

        nbar++; grid_sync(phase0 + nbar);
    }
}

// ---------------------------------------------------------------
extern "C" void kernel_launch(void* const* d_in, const int* in_sizes, int n_in,
                              void* d_out, int out_size) {
    const float* x    = (const float*)d_in[0];   // [B, T, I]
    const float* Wx   = (const float*)d_in[1];   // [I, 4H]
    const float* Wh   = (const float*)d_in[2];   // [H, 4H]
    const float* bias = (const float*)d_in[3];   // [4H]
    float* out = (float*)d_out;                  // [B, T, H]

    const int rec_smem = 131072 + 4 * 16384;     // 192 KB
    cudaFuncSetAttribute(lstm_tc_kernel,
                         cudaFuncAttributeMaxDynamicSharedMemorySize, rec_smem);

    split_x_kernel<<<(Bq * Tq * Iq / 2) / 256, 256>>>(x);
    split_w_kernel<<<G4 / 256, 256>>>(Wx);
    gemm_xproj_mma<<<(Bq * Tq / 128) * (G4 / 128), 256>>>(bias);
    lstm_tc_kernel<<<NBLK, 256, rec_smem>>>(Wh, out);
}